// round 1
// baseline (speedup 1.0000x reference)
#include <cuda_runtime.h>
#include <cuda_bf16.h>
#include <math.h>

#define N_NODES 50000
#define N_EDGES 500000
#define D 128

// ---------------- device scratch (no allocations allowed) ----------------
__device__ int   g_is64;
__device__ int   g_src[N_EDGES];
__device__ int   g_dst[N_EDGES];
__device__ int   g_cnt[N_NODES];
__device__ int   g_cursor[N_NODES];
__device__ int   g_rowptr[N_NODES + 1];
__device__ int   g_csr_src[N_EDGES];
__device__ float g_csr_norm[N_EDGES];
__device__ float g_deg[N_NODES];
__device__ float g_dinv[N_NODES];
__device__ float g_xw[(size_t)N_NODES * D];   // X @ W (layer input after GEMM)
__device__ float g_h[(size_t)N_NODES * D];    // aggregated hidden state

// ---------------- dtype detection for edge_index (int32 vs int64) --------
// If stored as int64 (values < 2^31, non-negative), every odd 32-bit word of
// the first 2048 words is zero. If int32, odd words are random node ids.
__global__ void detect_kernel(const unsigned int* __restrict__ w) {
    __shared__ unsigned int acc;
    int t = threadIdx.x;                      // 1024 threads
    if (t == 0) acc = 0u;
    __syncthreads();
    unsigned int v = w[2 * t + 1];
    if (v) atomicOr(&acc, v);
    __syncthreads();
    if (t == 0) g_is64 = (acc == 0u) ? 1 : 0;
}

// ---------------- init: zero deg + counts --------------------------------
__global__ void init_kernel() {
    int i = blockIdx.x * blockDim.x + threadIdx.x;
    if (i < N_NODES) { g_deg[i] = 0.0f; g_cnt[i] = 0; }
}

// ---------------- decode edges + degree/count histogram ------------------
__global__ void decode_kernel(const void* __restrict__ ei,
                              const float* __restrict__ ew) {
    int e = blockIdx.x * blockDim.x + threadIdx.x;
    if (e >= N_EDGES) return;
    int s, d;
    if (g_is64) {
        const long long* p = (const long long*)ei;
        s = (int)p[e];
        d = (int)p[N_EDGES + e];
    } else {
        const int* p = (const int*)ei;
        s = p[e];
        d = p[N_EDGES + e];
    }
    g_src[e] = s;
    g_dst[e] = d;
    atomicAdd(&g_deg[d], ew[e]);
    atomicAdd(&g_cnt[d], 1);
}

// ---------------- single-block exclusive scan of counts ------------------
__global__ void scan_kernel() {
    __shared__ int wsum[32];
    __shared__ int s_carry;
    int tid = threadIdx.x;                    // 1024 threads
    int lane = tid & 31, w = tid >> 5;
    if (tid == 0) s_carry = 0;
    __syncthreads();
    for (int base = 0; base < N_NODES; base += 1024) {
        int idx = base + tid;
        int v = (idx < N_NODES) ? g_cnt[idx] : 0;
        int x = v;
        #pragma unroll
        for (int o = 1; o < 32; o <<= 1) {
            int y = __shfl_up_sync(0xFFFFFFFFu, x, o);
            if (lane >= o) x += y;
        }
        if (lane == 31) wsum[w] = x;
        __syncthreads();
        if (w == 0) {
            int sv = wsum[lane];
            #pragma unroll
            for (int o = 1; o < 32; o <<= 1) {
                int y = __shfl_up_sync(0xFFFFFFFFu, sv, o);
                if (lane >= o) sv += y;
            }
            wsum[lane] = sv;
        }
        __syncthreads();
        int incl = x + (w > 0 ? wsum[w - 1] : 0);
        int excl = incl - v;
        int c = s_carry;
        if (idx < N_NODES) {
            int rp = c + excl;
            g_rowptr[idx] = rp;
            g_cursor[idx] = rp;
        }
        __syncthreads();
        if (tid == 1023) s_carry = c + incl;
        __syncthreads();
    }
    if (tid == 0) g_rowptr[N_NODES] = s_carry;
}

// ---------------- dinv ----------------------------------------------------
__global__ void dinv_kernel() {
    int i = blockIdx.x * blockDim.x + threadIdx.x;
    if (i < N_NODES) g_dinv[i] = rsqrtf(g_deg[i] + 1.0f);
}

// ---------------- CSR fill (per-edge norm precomputed, shared by layers) --
__global__ void fill_kernel(const float* __restrict__ ew) {
    int e = blockIdx.x * blockDim.x + threadIdx.x;
    if (e >= N_EDGES) return;
    int s = g_src[e];
    int d = g_dst[e];
    float nm = g_dinv[s] * ew[e] * g_dinv[d];
    int pos = atomicAdd(&g_cursor[d], 1);
    g_csr_src[pos] = s;
    g_csr_norm[pos] = nm;
}

// ---------------- fp32 GEMM: C[M,128] = A[M,128] @ W[128,128] -------------
// BM=64, 256 threads, thread tile 4 rows x 8 cols. A tile + W chunk in SMEM.
__global__ __launch_bounds__(256) void gemm_kernel(const float* __restrict__ A_ext,
                                                   const float* __restrict__ W,
                                                   int use_h, int M) {
    __shared__ float a_s[64][132];
    __shared__ float w_s[16][128];
    const float* A = use_h ? (const float*)g_h : A_ext;
    int tid = threadIdx.x;
    int row0 = blockIdx.x * 64;

    // load A tile (64x128) coalesced, zero-fill out-of-range rows
    #pragma unroll
    for (int i = 0; i < 8; i++) {
        int f = i * 256 + tid;
        int r = f >> 5;
        int c4 = (f & 31) * 4;
        float4 v = make_float4(0.f, 0.f, 0.f, 0.f);
        if (row0 + r < M)
            v = *(const float4*)(A + (size_t)(row0 + r) * D + c4);
        *(float4*)&a_s[r][c4] = v;
    }

    int ty = tid >> 4;        // 0..15 -> 4 rows each
    int tx = tid & 15;        // 0..15 -> 8 cols each
    float acc[4][8];
    #pragma unroll
    for (int i = 0; i < 4; i++)
        #pragma unroll
        for (int j = 0; j < 8; j++) acc[i][j] = 0.0f;

    for (int kc = 0; kc < 8; kc++) {
        // load W chunk (16x128)
        #pragma unroll
        for (int i = 0; i < 2; i++) {
            int f = i * 256 + tid;
            int r = f >> 5;
            int c4 = (f & 31) * 4;
            *(float4*)&w_s[r][c4] =
                *(const float4*)(W + (size_t)(kc * 16 + r) * D + c4);
        }
        __syncthreads();
        #pragma unroll
        for (int kk = 0; kk < 16; kk++) {
            int k = kc * 16 + kk;
            float a0 = a_s[ty * 4 + 0][k];
            float a1 = a_s[ty * 4 + 1][k];
            float a2 = a_s[ty * 4 + 2][k];
            float a3 = a_s[ty * 4 + 3][k];
            float4 b0 = *(const float4*)&w_s[kk][tx * 8];
            float4 b1 = *(const float4*)&w_s[kk][tx * 8 + 4];
            acc[0][0] += a0 * b0.x; acc[0][1] += a0 * b0.y;
            acc[0][2] += a0 * b0.z; acc[0][3] += a0 * b0.w;
            acc[0][4] += a0 * b1.x; acc[0][5] += a0 * b1.y;
            acc[0][6] += a0 * b1.z; acc[0][7] += a0 * b1.w;
            acc[1][0] += a1 * b0.x; acc[1][1] += a1 * b0.y;
            acc[1][2] += a1 * b0.z; acc[1][3] += a1 * b0.w;
            acc[1][4] += a1 * b1.x; acc[1][5] += a1 * b1.y;
            acc[1][6] += a1 * b1.z; acc[1][7] += a1 * b1.w;
            acc[2][0] += a2 * b0.x; acc[2][1] += a2 * b0.y;
            acc[2][2] += a2 * b0.z; acc[2][3] += a2 * b0.w;
            acc[2][4] += a2 * b1.x; acc[2][5] += a2 * b1.y;
            acc[2][6] += a2 * b1.z; acc[2][7] += a2 * b1.w;
            acc[3][0] += a3 * b0.x; acc[3][1] += a3 * b0.y;
            acc[3][2] += a3 * b0.z; acc[3][3] += a3 * b0.w;
            acc[3][4] += a3 * b1.x; acc[3][5] += a3 * b1.y;
            acc[3][6] += a3 * b1.z; acc[3][7] += a3 * b1.w;
        }
        __syncthreads();
    }

    #pragma unroll
    for (int i = 0; i < 4; i++) {
        int r = row0 + ty * 4 + i;
        if (r < M) {
            float* cp = g_xw + (size_t)r * D + tx * 8;
            *(float4*)cp       = make_float4(acc[i][0], acc[i][1], acc[i][2], acc[i][3]);
            *(float4*)(cp + 4) = make_float4(acc[i][4], acc[i][5], acc[i][6], acc[i][7]);
        }
    }
}

// ---------------- gather-aggregate: h[n] = b + dinv_n^2*xw[n] + sum norm*xw[src]
// warp per node, lane = float4 feature chunk. No atomics; xw lives in L2.
__global__ __launch_bounds__(256) void agg_kernel(const float* __restrict__ bias) {
    int gwarp = (blockIdx.x * blockDim.x + threadIdx.x) >> 5;
    int lane = threadIdx.x & 31;
    if (gwarp >= N_NODES) return;
    int n = gwarp;

    float di = g_dinv[n];
    float sl = di * di;
    const float4* xwrow = (const float4*)(g_xw + (size_t)n * D);
    float4 self = xwrow[lane];
    float4 bv = ((const float4*)bias)[lane];
    float4 acc;
    acc.x = fmaf(self.x, sl, bv.x);
    acc.y = fmaf(self.y, sl, bv.y);
    acc.z = fmaf(self.z, sl, bv.z);
    acc.w = fmaf(self.w, sl, bv.w);

    int k = g_rowptr[n];
    int end = g_rowptr[n + 1];
    if (k < end) {
        int s = g_csr_src[k];
        float nm = g_csr_norm[k];
        while (true) {
            int k2 = k + 1;
            int s2 = 0; float nm2 = 0.0f;
            if (k2 < end) { s2 = g_csr_src[k2]; nm2 = g_csr_norm[k2]; }
            float4 v = *(const float4*)(g_xw + (size_t)s * D + lane * 4);
            acc.x = fmaf(v.x, nm, acc.x);
            acc.y = fmaf(v.y, nm, acc.y);
            acc.z = fmaf(v.z, nm, acc.z);
            acc.w = fmaf(v.w, nm, acc.w);
            if (k2 >= end) break;
            k = k2; s = s2; nm = nm2;
        }
    }
    *(float4*)(g_h + (size_t)n * D + lane * 4) = acc;
}

// ---------------- final: sigmoid(h @ Wf + bf) * 10 -----------------------
__global__ __launch_bounds__(256) void final_kernel(const float* __restrict__ Wf,
                                                    const float* __restrict__ bf,
                                                    float* __restrict__ out) {
    int gwarp = (blockIdx.x * blockDim.x + threadIdx.x) >> 5;
    int lane = threadIdx.x & 31;
    if (gwarp >= N_NODES) return;
    int n = gwarp;
    float4 hv = *(const float4*)(g_h + (size_t)n * D + lane * 4);
    float4 wv = ((const float4*)Wf)[lane];
    float d = hv.x * wv.x + hv.y * wv.y + hv.z * wv.z + hv.w * wv.w;
    #pragma unroll
    for (int o = 16; o > 0; o >>= 1)
        d += __shfl_xor_sync(0xFFFFFFFFu, d, o);
    if (lane == 0) {
        float z = d + bf[0];
        out[n] = 10.0f / (1.0f + expf(-z));
    }
}

// ---------------- launcher ------------------------------------------------
extern "C" void kernel_launch(void* const* d_in, const int* in_sizes, int n_in,
                              void* d_out, int out_size) {
    const float* x  = (const float*)d_in[0];
    const void*  ei = d_in[1];
    const float* ew = (const float*)d_in[2];
    const float* W1 = (const float*)d_in[3];
    const float* b1 = (const float*)d_in[4];
    const float* W2 = (const float*)d_in[5];
    const float* b2 = (const float*)d_in[6];
    const float* Wf = (const float*)d_in[7];
    const float* bf = (const float*)d_in[8];
    float* out = (float*)d_out;

    const int NB = (N_NODES + 255) / 256;
    const int EB = (N_EDGES + 255) / 256;
    const int GB = (N_NODES + 63) / 64;             // gemm blocks
    const int WB = (N_NODES * 32 + 255) / 256;       // warp-per-node blocks

    detect_kernel<<<1, 1024>>>((const unsigned int*)ei);
    init_kernel<<<NB, 256>>>();
    decode_kernel<<<EB, 256>>>(ei, ew);
    scan_kernel<<<1, 1024>>>();
    dinv_kernel<<<NB, 256>>>();
    fill_kernel<<<EB, 256>>>(ew);

    // layer 1
    gemm_kernel<<<GB, 256>>>(x, W1, /*use_h=*/0, N_NODES);
    agg_kernel<<<WB, 256>>>(b1);
    // layer 2
    gemm_kernel<<<GB, 256>>>(nullptr, W2, /*use_h=*/1, N_NODES);
    agg_kernel<<<WB, 256>>>(b2);
    // head
    final_kernel<<<WB, 256>>>(Wf, bf, out);
}

// round 4
// speedup vs baseline: 1.7944x; 1.7944x over previous
#include <cuda_runtime.h>
#include <cuda_bf16.h>
#include <cstdint>
#include <math.h>

#define N_NODES 50000
#define N_EDGES 500000
#define D 128
#define TILE_M 128
#define N_TILES ((N_NODES + TILE_M - 1) / TILE_M)    // 391
#define SCAN_BLK 1024
#define N_SBLK ((N_NODES + SCAN_BLK - 1) / SCAN_BLK) // 49

// SMEM tile geometry (bf16, padded stride to kill ldmatrix bank conflicts)
#define TPAD 136
#define TILE_BYTES (128 * TPAD * 2)   // 34816
#define SM_AHI 0
#define SM_ALO (SM_AHI + TILE_BYTES)
#define SM_WHI (SM_ALO + TILE_BYTES)
#define SM_WLO (SM_WHI + TILE_BYTES)
#define SM_TOTAL (SM_WLO + TILE_BYTES)   // 139264

// ---------------- device scratch ----------------
__device__ int   g_is64;
__device__ int   g_src[N_EDGES];
__device__ int   g_dst[N_EDGES];
__device__ int   g_cnt[N_NODES];
__device__ int   g_cursor[N_NODES];
__device__ int   g_rowptr[N_NODES + 1];
__device__ int   g_csr_src[N_EDGES];
__device__ float g_csr_norm[N_EDGES];
__device__ float g_deg[N_NODES];
__device__ float g_dinv[N_NODES];
__device__ int   g_bsum[N_SBLK];
__device__ int   g_boff[N_SBLK];
__device__ float g_xw[(size_t)N_NODES * D];
__device__ float g_h[(size_t)N_NODES * D];
__device__ __nv_bfloat16 g_ahi[(size_t)N_NODES * D];
__device__ __nv_bfloat16 g_alo[(size_t)N_NODES * D];
__device__ __nv_bfloat16 g_wthi[2][D * D];   // W^T (n-major, k contiguous)
__device__ __nv_bfloat16 g_wtlo[2][D * D];

// ================= helpers =================
__device__ __forceinline__ uint32_t smem_u32(const void* p) {
    uint32_t a;
    asm("{ .reg .u64 t; cvta.to.shared.u64 t, %1; cvt.u32.u64 %0, t; }"
        : "=r"(a) : "l"(p));
    return a;
}
__device__ __forceinline__ void ldsm_x4(uint32_t* r, uint32_t addr) {
    asm volatile("ldmatrix.sync.aligned.m8n8.x4.shared.b16 {%0,%1,%2,%3}, [%4];"
        : "=r"(r[0]), "=r"(r[1]), "=r"(r[2]), "=r"(r[3]) : "r"(addr));
}
__device__ __forceinline__ void mma16816(float* c, const uint32_t* a,
                                         uint32_t b0, uint32_t b1) {
    asm volatile(
        "mma.sync.aligned.m16n8k16.row.col.f32.bf16.bf16.f32 "
        "{%0,%1,%2,%3}, {%4,%5,%6,%7}, {%8,%9}, {%0,%1,%2,%3};"
        : "+f"(c[0]), "+f"(c[1]), "+f"(c[2]), "+f"(c[3])
        : "r"(a[0]), "r"(a[1]), "r"(a[2]), "r"(a[3]), "r"(b0), "r"(b1));
}

// ================= preprocessing =================
__global__ void detect_kernel(const unsigned int* __restrict__ w) {
    __shared__ unsigned int acc;
    int t = threadIdx.x;
    if (t == 0) acc = 0u;
    __syncthreads();
    unsigned int v = w[2 * t + 1];
    if (v) atomicOr(&acc, v);
    __syncthreads();
    if (t == 0) g_is64 = (acc == 0u) ? 1 : 0;
}

__global__ void init_kernel() {
    int i = blockIdx.x * blockDim.x + threadIdx.x;
    if (i < N_NODES) { g_deg[i] = 0.0f; g_cnt[i] = 0; }
}

__global__ void decode_kernel(const void* __restrict__ ei,
                              const float* __restrict__ ew) {
    int e = blockIdx.x * blockDim.x + threadIdx.x;
    if (e >= N_EDGES) return;
    int s, d;
    if (g_is64) {
        const long long* p = (const long long*)ei;
        s = (int)p[e]; d = (int)p[N_EDGES + e];
    } else {
        const int* p = (const int*)ei;
        s = p[e]; d = p[N_EDGES + e];
    }
    g_src[e] = s; g_dst[e] = d;
    atomicAdd(&g_deg[d], ew[e]);
    atomicAdd(&g_cnt[d], 1);
}

// --- hierarchical scan ---
__global__ void scan_reduce_kernel() {
    __shared__ int ws[32];
    int tid = threadIdx.x, lane = tid & 31, w = tid >> 5;
    int idx = blockIdx.x * SCAN_BLK + tid;
    int v = (idx < N_NODES) ? g_cnt[idx] : 0;
    #pragma unroll
    for (int o = 16; o > 0; o >>= 1) v += __shfl_xor_sync(0xFFFFFFFFu, v, o);
    if (lane == 0) ws[w] = v;
    __syncthreads();
    if (w == 0) {
        int sv = ws[lane];
        #pragma unroll
        for (int o = 16; o > 0; o >>= 1) sv += __shfl_xor_sync(0xFFFFFFFFu, sv, o);
        if (lane == 0) g_bsum[blockIdx.x] = sv;
    }
}

__global__ void scan_mid_kernel() {
    if (threadIdx.x == 0) {
        int run = 0;
        for (int i = 0; i < N_SBLK; i++) { g_boff[i] = run; run += g_bsum[i]; }
        g_rowptr[N_NODES] = run;
    }
}

__global__ void scan_final_kernel() {
    __shared__ int ws[32];
    int tid = threadIdx.x, lane = tid & 31, w = tid >> 5;
    int idx = blockIdx.x * SCAN_BLK + tid;
    int v = (idx < N_NODES) ? g_cnt[idx] : 0;
    int x = v;
    #pragma unroll
    for (int o = 1; o < 32; o <<= 1) {
        int y = __shfl_up_sync(0xFFFFFFFFu, x, o);
        if (lane >= o) x += y;
    }
    if (lane == 31) ws[w] = x;
    __syncthreads();
    if (w == 0) {
        int sv = ws[lane];
        #pragma unroll
        for (int o = 1; o < 32; o <<= 1) {
            int y = __shfl_up_sync(0xFFFFFFFFu, sv, o);
            if (lane >= o) sv += y;
        }
        ws[lane] = sv;
    }
    __syncthreads();
    int excl = x - v + (w > 0 ? ws[w - 1] : 0) + g_boff[blockIdx.x];
    if (idx < N_NODES) { g_rowptr[idx] = excl; g_cursor[idx] = excl; }
}

__global__ void dinv_kernel() {
    int i = blockIdx.x * blockDim.x + threadIdx.x;
    if (i < N_NODES) g_dinv[i] = rsqrtf(g_deg[i] + 1.0f);
}

__global__ void fill_kernel(const float* __restrict__ ew) {
    int e = blockIdx.x * blockDim.x + threadIdx.x;
    if (e >= N_EDGES) return;
    int s = g_src[e], d = g_dst[e];
    float nm = g_dinv[s] * ew[e] * g_dinv[d];
    int pos = atomicAdd(&g_cursor[d], 1);
    g_csr_src[pos] = s;
    g_csr_norm[pos] = nm;
}

// ================= fp32 -> bf16 hi/lo split =================
__global__ __launch_bounds__(256) void split_x_kernel(const float* __restrict__ ext,
                                                      int use_h) {
    const float* src = use_h ? (const float*)g_h : ext;
    int i4 = blockIdx.x * blockDim.x + threadIdx.x;
    if (i4 >= N_NODES * D / 4) return;
    float4 v = ((const float4*)src)[i4];
    __nv_bfloat16 h0 = __float2bfloat16(v.x);
    __nv_bfloat16 h1 = __float2bfloat16(v.y);
    __nv_bfloat16 h2 = __float2bfloat16(v.z);
    __nv_bfloat16 h3 = __float2bfloat16(v.w);
    __nv_bfloat16 l0 = __float2bfloat16(v.x - __bfloat162float(h0));
    __nv_bfloat16 l1 = __float2bfloat16(v.y - __bfloat162float(h1));
    __nv_bfloat16 l2 = __float2bfloat16(v.z - __bfloat162float(h2));
    __nv_bfloat16 l3 = __float2bfloat16(v.w - __bfloat162float(h3));
    __nv_bfloat162* ph = (__nv_bfloat162*)g_ahi;
    __nv_bfloat162* pl = (__nv_bfloat162*)g_alo;
    ph[2 * i4]     = __nv_bfloat162(h0, h1);
    ph[2 * i4 + 1] = __nv_bfloat162(h2, h3);
    pl[2 * i4]     = __nv_bfloat162(l0, l1);
    pl[2 * i4 + 1] = __nv_bfloat162(l2, l3);
}

__global__ void split_w_kernel(const float* __restrict__ W, int which) {
    int i = blockIdx.x * blockDim.x + threadIdx.x;    // i = n*128 + k
    if (i >= D * D) return;
    int n = i >> 7, k = i & 127;
    float v = W[k * D + n];
    __nv_bfloat16 hi = __float2bfloat16(v);
    __nv_bfloat16 lo = __float2bfloat16(v - __bfloat162float(hi));
    g_wthi[which][i] = hi;
    g_wtlo[which][i] = lo;
}

// ================= HMMA GEMM: g_xw[tile] = A @ W =================
// 256 threads = 8 warps in a 4(M) x 2(N) grid. Warp tile: 32(M) x 64(N).
// 3 passes: Ahi*Whi, Ahi*Wlo, Alo*Whi, fp32 accumulated in registers.
__device__ __forceinline__ void stage_tile(char* sm, int off,
                                           const __nv_bfloat16* __restrict__ src,
                                           int row0, int maxrow, int tid) {
    #pragma unroll
    for (int it = 0; it < 8; it++) {
        int c = it * 256 + tid;         // 2048 16B-chunks
        int r = c >> 4;
        int col8 = (c & 15) * 8;
        uint4 v = make_uint4(0, 0, 0, 0);
        if (row0 + r < maxrow)
            v = *(const uint4*)(src + (size_t)(row0 + r) * D + col8);
        *(uint4*)(sm + off + (r * TPAD + col8) * 2) = v;
    }
}

__global__ __launch_bounds__(256, 1) void mma_gemm_kernel(int which) {
    extern __shared__ char smem[];
    uint32_t sbase = smem_u32(smem);
    int tid = threadIdx.x;
    int warp = tid >> 5, lane = tid & 31;
    int row0 = blockIdx.x * TILE_M;

    stage_tile(smem, SM_AHI, g_ahi, row0, N_NODES, tid);
    stage_tile(smem, SM_ALO, g_alo, row0, N_NODES, tid);
    stage_tile(smem, SM_WHI, g_wthi[which], 0, 128, tid);
    stage_tile(smem, SM_WLO, g_wtlo[which], 0, 128, tid);
    __syncthreads();

    int wm = warp >> 1;          // 0..3 : M group (32 rows)
    int wn = warp & 1;           // 0..1 : N group (64 cols)

    float acc[2][8][4];
    #pragma unroll
    for (int mi = 0; mi < 2; mi++)
        #pragma unroll
        for (int j = 0; j < 8; j++)
            #pragma unroll
            for (int q = 0; q < 4; q++) acc[mi][j][q] = 0.0f;

    // per-lane ldmatrix row/col selectors
    int arow = (lane & 7) + ((lane >> 3) & 1) * 8;   // + mi*16 + wm*32
    int acol = (lane >> 4) * 8;                      // + ks*16
    int brow = (lane & 7) + (lane >> 4) * 8;         // + j*16 + wn*64
    int bcol = ((lane >> 3) & 1) * 8;                // + ks*16

    #pragma unroll
    for (int pass = 0; pass < 3; pass++) {
        int aoff = (pass == 2) ? SM_ALO : SM_AHI;
        int boff = (pass == 1) ? SM_WLO : SM_WHI;
        #pragma unroll
        for (int ks = 0; ks < 8; ks++) {
            uint32_t a[2][4];
            #pragma unroll
            for (int mi = 0; mi < 2; mi++) {
                uint32_t addr = sbase + aoff +
                    ((wm * 32 + mi * 16 + arow) * TPAD + ks * 16 + acol) * 2;
                ldsm_x4(a[mi], addr);
            }
            uint32_t b[4][4];
            #pragma unroll
            for (int j = 0; j < 4; j++) {
                uint32_t addr = sbase + boff +
                    ((wn * 64 + j * 16 + brow) * TPAD + ks * 16 + bcol) * 2;
                ldsm_x4(b[j], addr);
            }
            #pragma unroll
            for (int mi = 0; mi < 2; mi++)
                #pragma unroll
                for (int j = 0; j < 4; j++) {
                    mma16816(acc[mi][2 * j],     a[mi], b[j][0], b[j][1]);
                    mma16816(acc[mi][2 * j + 1], a[mi], b[j][2], b[j][3]);
                }
        }
    }

    // epilogue: c0,c1 -> (row g, cols 2c,2c+1); c2,c3 -> (row g+8)
    int g = lane >> 2, cc = lane & 3;
    #pragma unroll
    for (int mi = 0; mi < 2; mi++) {
        int r_hi = row0 + wm * 32 + mi * 16 + g;
        #pragma unroll
        for (int j = 0; j < 8; j++) {
            int n0 = wn * 64 + j * 8 + 2 * cc;
            if (r_hi < N_NODES)
                *(float2*)(g_xw + (size_t)r_hi * D + n0) =
                    make_float2(acc[mi][j][0], acc[mi][j][1]);
            if (r_hi + 8 < N_NODES)
                *(float2*)(g_xw + (size_t)(r_hi + 8) * D + n0) =
                    make_float2(acc[mi][j][2], acc[mi][j][3]);
        }
    }
}

// ================= aggregation =================
__global__ __launch_bounds__(256) void agg_kernel(const float* __restrict__ bias) {
    int gwarp = (blockIdx.x * blockDim.x + threadIdx.x) >> 5;
    int lane = threadIdx.x & 31;
    if (gwarp >= N_NODES) return;
    int n = gwarp;
    float di = g_dinv[n];
    float sl = di * di;
    float4 self = ((const float4*)(g_xw + (size_t)n * D))[lane];
    float4 bv = ((const float4*)bias)[lane];
    float4 acc;
    acc.x = fmaf(self.x, sl, bv.x);
    acc.y = fmaf(self.y, sl, bv.y);
    acc.z = fmaf(self.z, sl, bv.z);
    acc.w = fmaf(self.w, sl, bv.w);
    int k = g_rowptr[n], end = g_rowptr[n + 1];
    for (; k < end; k++) {
        int s = g_csr_src[k];
        float nm = g_csr_norm[k];
        float4 v = *(const float4*)(g_xw + (size_t)s * D + lane * 4);
        acc.x = fmaf(v.x, nm, acc.x);
        acc.y = fmaf(v.y, nm, acc.y);
        acc.z = fmaf(v.z, nm, acc.z);
        acc.w = fmaf(v.w, nm, acc.w);
    }
    *(float4*)(g_h + (size_t)n * D + lane * 4) = acc;
}

// layer-2 aggregation fused with final head
__global__ __launch_bounds__(256) void agg_final_kernel(const float* __restrict__ bias,
                                                        const float* __restrict__ Wf,
                                                        const float* __restrict__ bf,
                                                        float* __restrict__ out) {
    int gwarp = (blockIdx.x * blockDim.x + threadIdx.x) >> 5;
    int lane = threadIdx.x & 31;
    if (gwarp >= N_NODES) return;
    int n = gwarp;
    float di = g_dinv[n];
    float sl = di * di;
    float4 self = ((const float4*)(g_xw + (size_t)n * D))[lane];
    float4 bv = ((const float4*)bias)[lane];
    float4 acc;
    acc.x = fmaf(self.x, sl, bv.x);
    acc.y = fmaf(self.y, sl, bv.y);
    acc.z = fmaf(self.z, sl, bv.z);
    acc.w = fmaf(self.w, sl, bv.w);
    int k = g_rowptr[n], end = g_rowptr[n + 1];
    for (; k < end; k++) {
        int s = g_csr_src[k];
        float nm = g_csr_norm[k];
        float4 v = *(const float4*)(g_xw + (size_t)s * D + lane * 4);
        acc.x = fmaf(v.x, nm, acc.x);
        acc.y = fmaf(v.y, nm, acc.y);
        acc.z = fmaf(v.z, nm, acc.z);
        acc.w = fmaf(v.w, nm, acc.w);
    }
    float4 wv = ((const float4*)Wf)[lane];
    float d = acc.x * wv.x + acc.y * wv.y + acc.z * wv.z + acc.w * wv.w;
    #pragma unroll
    for (int o = 16; o > 0; o >>= 1)
        d += __shfl_xor_sync(0xFFFFFFFFu, d, o);
    if (lane == 0) {
        float z = d + bf[0];
        out[n] = 10.0f / (1.0f + expf(-z));
    }
}

// ================= launcher =================
extern "C" void kernel_launch(void* const* d_in, const int* in_sizes, int n_in,
                              void* d_out, int out_size) {
    const float* x  = (const float*)d_in[0];
    const void*  ei = d_in[1];
    const float* ew = (const float*)d_in[2];
    const float* W1 = (const float*)d_in[3];
    const float* b1 = (const float*)d_in[4];
    const float* W2 = (const float*)d_in[5];
    const float* b2 = (const float*)d_in[6];
    const float* Wf = (const float*)d_in[7];
    const float* bf = (const float*)d_in[8];
    float* out = (float*)d_out;

    cudaFuncSetAttribute(mma_gemm_kernel,
                         cudaFuncAttributeMaxDynamicSharedMemorySize, SM_TOTAL);

    const int NB = (N_NODES + 255) / 256;
    const int EB = (N_EDGES + 255) / 256;
    const int WB = (N_NODES * 32 + 255) / 256;
    const int SB = (N_NODES * D / 4 + 255) / 256;

    detect_kernel<<<1, 1024>>>((const unsigned int*)ei);
    init_kernel<<<NB, 256>>>();
    decode_kernel<<<EB, 256>>>(ei, ew);
    scan_reduce_kernel<<<N_SBLK, SCAN_BLK>>>();
    scan_mid_kernel<<<1, 32>>>();
    scan_final_kernel<<<N_SBLK, SCAN_BLK>>>();
    dinv_kernel<<<NB, 256>>>();
    fill_kernel<<<EB, 256>>>(ew);

    split_w_kernel<<<(D * D + 255) / 256, 256>>>(W1, 0);
    split_w_kernel<<<(D * D + 255) / 256, 256>>>(W2, 1);

    // layer 1
    split_x_kernel<<<SB, 256>>>(x, 0);
    mma_gemm_kernel<<<N_TILES, 256, SM_TOTAL>>>(0);
    agg_kernel<<<WB, 256>>>(b1);
    // layer 2 (agg fused with final head)
    split_x_kernel<<<SB, 256>>>(nullptr, 1);
    mma_gemm_kernel<<<N_TILES, 256, SM_TOTAL>>>(1);
    agg_final_kernel<<<WB, 256>>>(b2, Wf, bf, out);
}

// round 5
// speedup vs baseline: 2.0885x; 1.1639x over previous
#include <cuda_runtime.h>
#include <cuda_bf16.h>
#include <cstdint>
#include <math.h>

#define N_NODES 50000
#define N_EDGES 500000
#define D 128
#define TILE_M 128
#define N_TILES ((N_NODES + TILE_M - 1) / TILE_M)    // 391
#define SCAN_BLK 1024
#define N_SBLK ((N_NODES + SCAN_BLK - 1) / SCAN_BLK) // 49

// SMEM tile geometry (bf16, padded stride to kill ldmatrix bank conflicts)
#define TPAD 136
#define TILE_BYTES (128 * TPAD * 2)   // 34816
#define SM_AHI 0
#define SM_ALO (SM_AHI + TILE_BYTES)
#define SM_WHI (SM_ALO + TILE_BYTES)
#define SM_WLO (SM_WHI + TILE_BYTES)
#define SM_TOTAL (SM_WLO + TILE_BYTES)   // 139264

// ---------------- device scratch ----------------
__device__ int   g_is64;
__device__ int   g_src[N_EDGES];
__device__ int   g_dst[N_EDGES];
__device__ int   g_cnt[N_NODES];
__device__ int   g_cursor[N_NODES];
__device__ int   g_rowptr[N_NODES + 1];
__device__ int   g_csr_src[N_EDGES];
__device__ float g_csr_norm[N_EDGES];
__device__ float g_deg[N_NODES];
__device__ float g_dinv[N_NODES];
__device__ int   g_bsum[N_SBLK];
__device__ int   g_boff[N_SBLK];
__device__ float g_xw[(size_t)N_NODES * D];
__device__ __nv_bfloat16 g_ahi[(size_t)N_NODES * D];
__device__ __nv_bfloat16 g_alo[(size_t)N_NODES * D];
__device__ __nv_bfloat16 g_wthi[2][D * D];   // W^T (n-major, k contiguous)
__device__ __nv_bfloat16 g_wtlo[2][D * D];

// ================= helpers =================
__device__ __forceinline__ uint32_t smem_u32(const void* p) {
    uint32_t a;
    asm("{ .reg .u64 t; cvta.to.shared.u64 t, %1; cvt.u32.u64 %0, t; }"
        : "=r"(a) : "l"(p));
    return a;
}
__device__ __forceinline__ void ldsm_x4(uint32_t* r, uint32_t addr) {
    asm volatile("ldmatrix.sync.aligned.m8n8.x4.shared.b16 {%0,%1,%2,%3}, [%4];"
        : "=r"(r[0]), "=r"(r[1]), "=r"(r[2]), "=r"(r[3]) : "r"(addr));
}
__device__ __forceinline__ void mma16816(float* c, const uint32_t* a,
                                         uint32_t b0, uint32_t b1) {
    asm volatile(
        "mma.sync.aligned.m16n8k16.row.col.f32.bf16.bf16.f32 "
        "{%0,%1,%2,%3}, {%4,%5,%6,%7}, {%8,%9}, {%0,%1,%2,%3};"
        : "+f"(c[0]), "+f"(c[1]), "+f"(c[2]), "+f"(c[3])
        : "r"(a[0]), "r"(a[1]), "r"(a[2]), "r"(a[3]), "r"(b0), "r"(b1));
}
__device__ __forceinline__ uint32_t pack_hi2(float a, float b) {
    __nv_bfloat162 h(__float2bfloat16(a), __float2bfloat16(b));
    return *(uint32_t*)&h;
}
__device__ __forceinline__ uint32_t pack_lo2(float a, float b) {
    __nv_bfloat16 ha = __float2bfloat16(a), hb = __float2bfloat16(b);
    __nv_bfloat162 l(__float2bfloat16(a - __bfloat162float(ha)),
                     __float2bfloat16(b - __bfloat162float(hb)));
    return *(uint32_t*)&l;
}

// ================= preprocessing =================
__global__ void detect_kernel(const unsigned int* __restrict__ w) {
    __shared__ unsigned int acc;
    int t = threadIdx.x;
    if (t == 0) acc = 0u;
    __syncthreads();
    unsigned int v = w[2 * t + 1];
    if (v) atomicOr(&acc, v);
    __syncthreads();
    if (t == 0) g_is64 = (acc == 0u) ? 1 : 0;
}

__global__ void init_kernel() {
    int i = blockIdx.x * blockDim.x + threadIdx.x;
    if (i < N_NODES) { g_deg[i] = 0.0f; g_cnt[i] = 0; }
}

__global__ void decode_kernel(const void* __restrict__ ei,
                              const float* __restrict__ ew) {
    int e = blockIdx.x * blockDim.x + threadIdx.x;
    if (e >= N_EDGES) return;
    int s, d;
    if (g_is64) {
        const long long* p = (const long long*)ei;
        s = (int)p[e]; d = (int)p[N_EDGES + e];
    } else {
        const int* p = (const int*)ei;
        s = p[e]; d = p[N_EDGES + e];
    }
    g_src[e] = s; g_dst[e] = d;
    atomicAdd(&g_deg[d], ew[e]);
    atomicAdd(&g_cnt[d], 1);
}

// --- hierarchical scan ---
__global__ void scan_reduce_kernel() {
    __shared__ int ws[32];
    int tid = threadIdx.x, lane = tid & 31, w = tid >> 5;
    int idx = blockIdx.x * SCAN_BLK + tid;
    int v = (idx < N_NODES) ? g_cnt[idx] : 0;
    #pragma unroll
    for (int o = 16; o > 0; o >>= 1) v += __shfl_xor_sync(0xFFFFFFFFu, v, o);
    if (lane == 0) ws[w] = v;
    __syncthreads();
    if (w == 0) {
        int sv = ws[lane];
        #pragma unroll
        for (int o = 16; o > 0; o >>= 1) sv += __shfl_xor_sync(0xFFFFFFFFu, sv, o);
        if (lane == 0) g_bsum[blockIdx.x] = sv;
    }
}

__global__ void scan_mid_kernel() {
    if (threadIdx.x == 0) {
        int run = 0;
        for (int i = 0; i < N_SBLK; i++) { g_boff[i] = run; run += g_bsum[i]; }
        g_rowptr[N_NODES] = run;
    }
}

__global__ void scan_final_kernel() {
    __shared__ int ws[32];
    int tid = threadIdx.x, lane = tid & 31, w = tid >> 5;
    int idx = blockIdx.x * SCAN_BLK + tid;
    int v = (idx < N_NODES) ? g_cnt[idx] : 0;
    int x = v;
    #pragma unroll
    for (int o = 1; o < 32; o <<= 1) {
        int y = __shfl_up_sync(0xFFFFFFFFu, x, o);
        if (lane >= o) x += y;
    }
    if (lane == 31) ws[w] = x;
    __syncthreads();
    if (w == 0) {
        int sv = ws[lane];
        #pragma unroll
        for (int o = 1; o < 32; o <<= 1) {
            int y = __shfl_up_sync(0xFFFFFFFFu, sv, o);
            if (lane >= o) sv += y;
        }
        ws[lane] = sv;
    }
    __syncthreads();
    int excl = x - v + (w > 0 ? ws[w - 1] : 0) + g_boff[blockIdx.x];
    if (idx < N_NODES) { g_rowptr[idx] = excl; g_cursor[idx] = excl; }
}

__global__ void dinv_kernel() {
    int i = blockIdx.x * blockDim.x + threadIdx.x;
    if (i < N_NODES) g_dinv[i] = rsqrtf(g_deg[i] + 1.0f);
}

__global__ void fill_kernel(const float* __restrict__ ew) {
    int e = blockIdx.x * blockDim.x + threadIdx.x;
    if (e >= N_EDGES) return;
    int s = g_src[e], d = g_dst[e];
    float nm = g_dinv[s] * ew[e] * g_dinv[d];
    int pos = atomicAdd(&g_cursor[d], 1);
    g_csr_src[pos] = s;
    g_csr_norm[pos] = nm;
}

// ================= weight split (tiny) =================
__global__ void split_w_kernel(const float* __restrict__ W, int which) {
    int i = blockIdx.x * blockDim.x + threadIdx.x;    // i = n*128 + k
    if (i >= D * D) return;
    int n = i >> 7, k = i & 127;
    float v = W[k * D + n];
    __nv_bfloat16 hi = __float2bfloat16(v);
    __nv_bfloat16 lo = __float2bfloat16(v - __bfloat162float(hi));
    g_wthi[which][i] = hi;
    g_wtlo[which][i] = lo;
}

// ================= HMMA GEMM =================
// 256 threads = 8 warps, 4(M) x 2(N). Warp tile 32(M) x 64(N).
// 3 passes: Ahi*Whi, Ahi*Wlo, Alo*Whi, fp32 register accum.
__device__ __forceinline__ void stage_tile(char* sm, int off,
                                           const __nv_bfloat16* __restrict__ src,
                                           int row0, int maxrow, int tid) {
    #pragma unroll
    for (int it = 0; it < 8; it++) {
        int c = it * 256 + tid;         // 2048 16B-chunks
        int r = c >> 4;
        int col8 = (c & 15) * 8;
        uint4 v = make_uint4(0, 0, 0, 0);
        if (row0 + r < maxrow)
            v = *(const uint4*)(src + (size_t)(row0 + r) * D + col8);
        *(uint4*)(sm + off + (r * TPAD + col8) * 2) = v;
    }
}

// stage fp32 source, splitting into hi/lo bf16 tiles on the fly
__device__ __forceinline__ void stage_x_split(char* sm,
                                              const float* __restrict__ src,
                                              int row0, int tid) {
    #pragma unroll
    for (int it = 0; it < 16; it++) {
        int c = it * 256 + tid;         // 4096 float4-chunks
        int r = c >> 5;
        int col4 = (c & 31) * 4;
        float4 v = make_float4(0.f, 0.f, 0.f, 0.f);
        if (row0 + r < N_NODES)
            v = *(const float4*)(src + (size_t)(row0 + r) * D + col4);
        uint2 hi, lo;
        hi.x = pack_hi2(v.x, v.y); hi.y = pack_hi2(v.z, v.w);
        lo.x = pack_lo2(v.x, v.y); lo.y = pack_lo2(v.z, v.w);
        *(uint2*)(sm + SM_AHI + (r * TPAD + col4) * 2) = hi;
        *(uint2*)(sm + SM_ALO + (r * TPAD + col4) * 2) = lo;
    }
}

__global__ __launch_bounds__(256, 1) void mma_gemm_kernel(const float* __restrict__ xsrc,
                                                          int use_x, int which) {
    extern __shared__ char smem[];
    uint32_t sbase = smem_u32(smem);
    int tid = threadIdx.x;
    int warp = tid >> 5, lane = tid & 31;
    int row0 = blockIdx.x * TILE_M;

    if (use_x) {
        stage_x_split(smem, xsrc, row0, tid);
    } else {
        stage_tile(smem, SM_AHI, g_ahi, row0, N_NODES, tid);
        stage_tile(smem, SM_ALO, g_alo, row0, N_NODES, tid);
    }
    stage_tile(smem, SM_WHI, g_wthi[which], 0, 128, tid);
    stage_tile(smem, SM_WLO, g_wtlo[which], 0, 128, tid);
    __syncthreads();

    int wm = warp >> 1;          // 0..3 : M group (32 rows)
    int wn = warp & 1;           // 0..1 : N group (64 cols)

    float acc[2][8][4];
    #pragma unroll
    for (int mi = 0; mi < 2; mi++)
        #pragma unroll
        for (int j = 0; j < 8; j++)
            #pragma unroll
            for (int q = 0; q < 4; q++) acc[mi][j][q] = 0.0f;

    int arow = (lane & 7) + ((lane >> 3) & 1) * 8;
    int acol = (lane >> 4) * 8;
    int brow = (lane & 7) + (lane >> 4) * 8;
    int bcol = ((lane >> 3) & 1) * 8;

    #pragma unroll
    for (int pass = 0; pass < 3; pass++) {
        int aoff = (pass == 2) ? SM_ALO : SM_AHI;
        int boff = (pass == 1) ? SM_WLO : SM_WHI;
        #pragma unroll
        for (int ks = 0; ks < 8; ks++) {
            uint32_t a[2][4];
            #pragma unroll
            for (int mi = 0; mi < 2; mi++) {
                uint32_t addr = sbase + aoff +
                    ((wm * 32 + mi * 16 + arow) * TPAD + ks * 16 + acol) * 2;
                ldsm_x4(a[mi], addr);
            }
            uint32_t b[4][4];
            #pragma unroll
            for (int j = 0; j < 4; j++) {
                uint32_t addr = sbase + boff +
                    ((wn * 64 + j * 16 + brow) * TPAD + ks * 16 + bcol) * 2;
                ldsm_x4(b[j], addr);
            }
            #pragma unroll
            for (int mi = 0; mi < 2; mi++)
                #pragma unroll
                for (int j = 0; j < 4; j++) {
                    mma16816(acc[mi][2 * j],     a[mi], b[j][0], b[j][1]);
                    mma16816(acc[mi][2 * j + 1], a[mi], b[j][2], b[j][3]);
                }
        }
    }

    int g = lane >> 2, cc = lane & 3;
    #pragma unroll
    for (int mi = 0; mi < 2; mi++) {
        int r_hi = row0 + wm * 32 + mi * 16 + g;
        #pragma unroll
        for (int j = 0; j < 8; j++) {
            int n0 = wn * 64 + j * 8 + 2 * cc;
            if (r_hi < N_NODES)
                *(float2*)(g_xw + (size_t)r_hi * D + n0) =
                    make_float2(acc[mi][j][0], acc[mi][j][1]);
            if (r_hi + 8 < N_NODES)
                *(float2*)(g_xw + (size_t)(r_hi + 8) * D + n0) =
                    make_float2(acc[mi][j][2], acc[mi][j][3]);
        }
    }
}

// ================= aggregation (layer 1): emits bf16 hi/lo directly ======
__global__ __launch_bounds__(256) void agg_split_kernel(const float* __restrict__ bias) {
    int gwarp = (blockIdx.x * blockDim.x + threadIdx.x) >> 5;
    int lane = threadIdx.x & 31;
    if (gwarp >= N_NODES) return;
    int n = gwarp;
    float di = g_dinv[n];
    float sl = di * di;
    float4 self = ((const float4*)(g_xw + (size_t)n * D))[lane];
    float4 bv = ((const float4*)bias)[lane];
    float4 acc;
    acc.x = fmaf(self.x, sl, bv.x);
    acc.y = fmaf(self.y, sl, bv.y);
    acc.z = fmaf(self.z, sl, bv.z);
    acc.w = fmaf(self.w, sl, bv.w);
    int k = g_rowptr[n], end = g_rowptr[n + 1];
    if (k < end) {
        int s = g_csr_src[k];
        float nm = g_csr_norm[k];
        float4 v = *(const float4*)(g_xw + (size_t)s * D + lane * 4);
        for (k = k + 1; k < end; k++) {
            int s2 = g_csr_src[k];
            float nm2 = g_csr_norm[k];
            float4 v2 = *(const float4*)(g_xw + (size_t)s2 * D + lane * 4);
            acc.x = fmaf(v.x, nm, acc.x);
            acc.y = fmaf(v.y, nm, acc.y);
            acc.z = fmaf(v.z, nm, acc.z);
            acc.w = fmaf(v.w, nm, acc.w);
            v = v2; nm = nm2;
        }
        acc.x = fmaf(v.x, nm, acc.x);
        acc.y = fmaf(v.y, nm, acc.y);
        acc.z = fmaf(v.z, nm, acc.z);
        acc.w = fmaf(v.w, nm, acc.w);
    }
    uint2 hi, lo;
    hi.x = pack_hi2(acc.x, acc.y); hi.y = pack_hi2(acc.z, acc.w);
    lo.x = pack_lo2(acc.x, acc.y); lo.y = pack_lo2(acc.z, acc.w);
    *(uint2*)(g_ahi + (size_t)n * D + lane * 4) = hi;
    *(uint2*)(g_alo + (size_t)n * D + lane * 4) = lo;
}

// layer-2 aggregation fused with final head
__global__ __launch_bounds__(256) void agg_final_kernel(const float* __restrict__ bias,
                                                        const float* __restrict__ Wf,
                                                        const float* __restrict__ bf,
                                                        float* __restrict__ out) {
    int gwarp = (blockIdx.x * blockDim.x + threadIdx.x) >> 5;
    int lane = threadIdx.x & 31;
    if (gwarp >= N_NODES) return;
    int n = gwarp;
    float di = g_dinv[n];
    float sl = di * di;
    float4 self = ((const float4*)(g_xw + (size_t)n * D))[lane];
    float4 bv = ((const float4*)bias)[lane];
    float4 acc;
    acc.x = fmaf(self.x, sl, bv.x);
    acc.y = fmaf(self.y, sl, bv.y);
    acc.z = fmaf(self.z, sl, bv.z);
    acc.w = fmaf(self.w, sl, bv.w);
    int k = g_rowptr[n], end = g_rowptr[n + 1];
    if (k < end) {
        int s = g_csr_src[k];
        float nm = g_csr_norm[k];
        float4 v = *(const float4*)(g_xw + (size_t)s * D + lane * 4);
        for (k = k + 1; k < end; k++) {
            int s2 = g_csr_src[k];
            float nm2 = g_csr_norm[k];
            float4 v2 = *(const float4*)(g_xw + (size_t)s2 * D + lane * 4);
            acc.x = fmaf(v.x, nm, acc.x);
            acc.y = fmaf(v.y, nm, acc.y);
            acc.z = fmaf(v.z, nm, acc.z);
            acc.w = fmaf(v.w, nm, acc.w);
            v = v2; nm = nm2;
        }
        acc.x = fmaf(v.x, nm, acc.x);
        acc.y = fmaf(v.y, nm, acc.y);
        acc.z = fmaf(v.z, nm, acc.z);
        acc.w = fmaf(v.w, nm, acc.w);
    }
    float4 wv = ((const float4*)Wf)[lane];
    float d = acc.x * wv.x + acc.y * wv.y + acc.z * wv.z + acc.w * wv.w;
    #pragma unroll
    for (int o = 16; o > 0; o >>= 1)
        d += __shfl_xor_sync(0xFFFFFFFFu, d, o);
    if (lane == 0) {
        float z = d + bf[0];
        out[n] = 10.0f / (1.0f + expf(-z));
    }
}

// ================= launcher =================
extern "C" void kernel_launch(void* const* d_in, const int* in_sizes, int n_in,
                              void* d_out, int out_size) {
    const float* x  = (const float*)d_in[0];
    const void*  ei = d_in[1];
    const float* ew = (const float*)d_in[2];
    const float* W1 = (const float*)d_in[3];
    const float* b1 = (const float*)d_in[4];
    const float* W2 = (const float*)d_in[5];
    const float* b2 = (const float*)d_in[6];
    const float* Wf = (const float*)d_in[7];
    const float* bf = (const float*)d_in[8];
    float* out = (float*)d_out;

    static cudaStream_t s_pre = nullptr;
    static cudaEvent_t ev_fork = nullptr, ev_join = nullptr;
    if (!s_pre) {
        cudaStreamCreateWithFlags(&s_pre, cudaStreamNonBlocking);
        cudaEventCreateWithFlags(&ev_fork, cudaEventDisableTiming);
        cudaEventCreateWithFlags(&ev_join, cudaEventDisableTiming);
        cudaFuncSetAttribute(mma_gemm_kernel,
                             cudaFuncAttributeMaxDynamicSharedMemorySize, SM_TOTAL);
    }

    const int NB = (N_NODES + 255) / 256;
    const int EB = (N_EDGES + 255) / 256;
    const int WB = (N_NODES * 32 + 255) / 256;

    // fork: preprocessing chain on side stream (independent of gemm1)
    cudaEventRecord(ev_fork, 0);
    cudaStreamWaitEvent(s_pre, ev_fork, 0);
    detect_kernel<<<1, 1024, 0, s_pre>>>((const unsigned int*)ei);
    init_kernel<<<NB, 256, 0, s_pre>>>();
    decode_kernel<<<EB, 256, 0, s_pre>>>(ei, ew);
    scan_reduce_kernel<<<N_SBLK, SCAN_BLK, 0, s_pre>>>();
    scan_mid_kernel<<<1, 32, 0, s_pre>>>();
    scan_final_kernel<<<N_SBLK, SCAN_BLK, 0, s_pre>>>();
    dinv_kernel<<<NB, 256, 0, s_pre>>>();
    fill_kernel<<<EB, 256, 0, s_pre>>>(ew);
    cudaEventRecord(ev_join, s_pre);

    // main stream: weights + gemm1 (x staged+split in-kernel)
    split_w_kernel<<<(D * D + 255) / 256, 256>>>(W1, 0);
    split_w_kernel<<<(D * D + 255) / 256, 256>>>(W2, 1);
    mma_gemm_kernel<<<N_TILES, 256, SM_TOTAL>>>(x, 1, 0);

    // join: aggregation needs CSR
    cudaStreamWaitEvent(0, ev_join, 0);
    agg_split_kernel<<<WB, 256>>>(b1);                 // emits bf16 hi/lo
    mma_gemm_kernel<<<N_TILES, 256, SM_TOTAL>>>(nullptr, 0, 1);
    agg_final_kernel<<<WB, 256>>>(b2, Wf, bf, out);
}